// round 1
// baseline (speedup 1.0000x reference)
#include <cuda_runtime.h>
#include <math.h>

#define B_TOK 32768
#define F_DIM 512
#define H_DIM 256
#define C_DIM 100
#define E_EXP 8

#define BM 64
#define BK 16

// scratch: gating weights [B,E]; fallback preds buffer in case d_out only holds 'combined'
__device__ float g_weights[B_TOK * E_EXP];
__device__ float g_preds_fallback[(size_t)E_EXP * B_TOK * C_DIM];

// ---------------------------------------------------------------------------
__global__ void zero_part_kernel(float* part) {
    if (threadIdx.x < E_EXP) part[threadIdx.x] = 0.0f;
}

// ---------------------------------------------------------------------------
// Gating: one warp per token row. softmax is monotonic -> top-k on raw logits.
__global__ void gating_kernel(const float* __restrict__ x,
                              const float* __restrict__ Wg,
                              float* __restrict__ part) {
    int warp = threadIdx.x >> 5;
    int lane = threadIdx.x & 31;
    int b = blockIdx.x * 8 + warp;
    if (b >= B_TOK) return;

    float acc[E_EXP];
#pragma unroll
    for (int e = 0; e < E_EXP; e++) acc[e] = 0.0f;

    const float* xrow = x + (size_t)b * F_DIM;
    for (int f = lane; f < F_DIM; f += 32) {
        float xv = xrow[f];
#pragma unroll
        for (int e = 0; e < E_EXP; e++) acc[e] += xv * Wg[f * E_EXP + e];
    }
#pragma unroll
    for (int off = 16; off; off >>= 1) {
#pragma unroll
        for (int e = 0; e < E_EXP; e++)
            acc[e] += __shfl_xor_sync(0xffffffffu, acc[e], off);
    }
    if (lane == 0) {
        int i1 = 0;
#pragma unroll
        for (int e = 1; e < E_EXP; e++) if (acc[e] > acc[i1]) i1 = e;
        int i2 = (i1 == 0) ? 1 : 0;
#pragma unroll
        for (int e = 0; e < E_EXP; e++)
            if (e != i1 && acc[e] > acc[i2]) i2 = e;
#pragma unroll
        for (int e = 0; e < E_EXP; e++)
            g_weights[b * E_EXP + e] = (e == i1 || e == i2) ? 0.5f : 0.0f;
        atomicAdd(&part[i1], 1.0f);
        atomicAdd(&part[i2], 1.0f);
    }
}

// ---------------------------------------------------------------------------
// Fused 2-layer expert MLP: one block = (64-token tile, one expert).
// GEMM1: h[64,256] = relu(x[64,512] @ W1e + b1) kept in SMEM.
// GEMM2: preds[64,100] = h @ W2e + b2, staged to SMEM, coalesced float4 store.
__global__ void __launch_bounds__(256, 2)
moe_mlp_kernel(const float* __restrict__ x,
               const float* __restrict__ W1,
               const float* __restrict__ b1,
               const float* __restrict__ W2,
               const float* __restrict__ b2,
               float* __restrict__ preds) {
    extern __shared__ float smem[];
    float* h_s  = smem;                  // [64][257] = 16448 floats
    float* As   = smem + 64 * 257;       // [16][68]  = 1088 floats
    float* Bs   = As + 16 * 68;          // [16][256] = 4096 floats
    float* w2_s = As;                    // overlay: [32][104] = 3328 <= 5184
    float* p_s  = h_s;                   // overlay after h consumed: 6400 floats

    const int t    = threadIdx.x;
    const int e    = blockIdx.y;
    const int row0 = blockIdx.x * BM;

    const float* W1e = W1 + (size_t)e * F_DIM * H_DIM;

    // thread tile for GEMM1: 16x16 thread grid, each 4 rows x 16 cols
    const int ty = t >> 4;
    const int tx = t & 15;

    float acc[4][16];
#pragma unroll
    for (int i = 0; i < 4; i++)
#pragma unroll
        for (int j = 0; j < 16; j++) acc[i][j] = 0.0f;

    const int ar = t >> 2, aq = t & 3;   // A-tile loader coords
    const int bk = t >> 4, bh = t & 15;  // B-tile loader coords

    for (int kt = 0; kt < F_DIM / BK; ++kt) {
        const int f0 = kt * BK;
        // load A tile (x) transposed into As[k][row], pitch 68
        float4 xv = *(const float4*)(x + (size_t)(row0 + ar) * F_DIM + f0 + aq * 4);
        As[(aq * 4 + 0) * 68 + ar] = xv.x;
        As[(aq * 4 + 1) * 68 + ar] = xv.y;
        As[(aq * 4 + 2) * 68 + ar] = xv.z;
        As[(aq * 4 + 3) * 68 + ar] = xv.w;
        // load B tile (W1e rows f0..f0+15, all 256 cols)
        const float4* wrow = (const float4*)(W1e + (size_t)(f0 + bk) * H_DIM + bh * 16);
        float4* bsrow = (float4*)(Bs + bk * 256 + bh * 16);
#pragma unroll
        for (int j = 0; j < 4; j++) bsrow[j] = wrow[j];
        __syncthreads();

#pragma unroll
        for (int k = 0; k < BK; k++) {
            float4 av = *(const float4*)(As + k * 68 + ty * 4);
            float a0 = av.x, a1 = av.y, a2 = av.z, a3 = av.w;
            const float4* brow = (const float4*)(Bs + k * 256 + tx * 16);
            float4 bv0 = brow[0], bv1 = brow[1], bv2 = brow[2], bv3 = brow[3];
            float bfr[16] = {bv0.x, bv0.y, bv0.z, bv0.w,
                             bv1.x, bv1.y, bv1.z, bv1.w,
                             bv2.x, bv2.y, bv2.z, bv2.w,
                             bv3.x, bv3.y, bv3.z, bv3.w};
#pragma unroll
            for (int j = 0; j < 16; j++) {
                acc[0][j] += a0 * bfr[j];
                acc[1][j] += a1 * bfr[j];
                acc[2][j] += a2 * bfr[j];
                acc[3][j] += a3 * bfr[j];
            }
        }
        __syncthreads();
    }

    // h = relu(acc + b1) -> SMEM
#pragma unroll
    for (int j = 0; j < 16; j++) {
        float b1v = b1[e * H_DIM + tx * 16 + j];
#pragma unroll
        for (int i = 0; i < 4; i++) {
            float v = acc[i][j] + b1v;
            h_s[(ty * 4 + i) * 257 + tx * 16 + j] = v > 0.0f ? v : 0.0f;
        }
    }
    __syncthreads();

    // GEMM2: thread -> (row = t&63, 25 cols starting at (t>>6)*25)
    const int row = t & 63;
    const int c0  = (t >> 6) * 25;
    float acc2[25];
#pragma unroll
    for (int j = 0; j < 25; j++) acc2[j] = 0.0f;

    const float* W2e = W2 + (size_t)e * H_DIM * C_DIM;
    for (int kc = 0; kc < H_DIM / 32; kc++) {
        for (int idx = t; idx < 32 * C_DIM; idx += 256) {
            int kk = idx / C_DIM;
            int c  = idx - kk * C_DIM;
            w2_s[kk * 104 + c] = W2e[(size_t)(kc * 32 + kk) * C_DIM + c];
        }
        __syncthreads();
#pragma unroll
        for (int kk = 0; kk < 32; kk++) {
            float hv = h_s[row * 257 + kc * 32 + kk];
#pragma unroll
            for (int j = 0; j < 25; j++)
                acc2[j] += hv * w2_s[kk * 104 + c0 + j];
        }
        __syncthreads();
    }

    // stage preds tile to SMEM (overlays h_s; safe after last sync)
#pragma unroll
    for (int j = 0; j < 25; j++)
        p_s[row * C_DIM + c0 + j] = acc2[j] + b2[e * C_DIM + c0 + j];
    __syncthreads();

    // coalesced float4 store: tile is contiguous in preds
    float4* po4 = (float4*)(preds + (size_t)e * B_TOK * C_DIM + (size_t)row0 * C_DIM);
    const float4* ps4 = (const float4*)p_s;
    for (int idx = t; idx < (BM * C_DIM) / 4; idx += 256) po4[idx] = ps4[idx];
}

// ---------------------------------------------------------------------------
// Combine: one warp per token row; softmax over C=100 for its 2 experts.
__global__ void combine_kernel(const float* __restrict__ preds,
                               float* __restrict__ combined) {
    int warp = threadIdx.x >> 5;
    int lane = threadIdx.x & 31;
    int b = blockIdx.x * 8 + warp;
    if (b >= B_TOK) return;

    float w = (lane < E_EXP) ? g_weights[b * E_EXP + lane] : 0.0f;
    unsigned mask = __ballot_sync(0xffffffffu, w > 0.0f);
    int e1 = __ffs(mask) - 1;
    int e2 = 31 - __clz(mask);

    float out[4] = {0.f, 0.f, 0.f, 0.f};
    int es[2] = {e1, e2};
#pragma unroll
    for (int s = 0; s < 2; s++) {
        const float* pr = preds + ((size_t)es[s] * B_TOK + b) * C_DIM;
        float v[4];
#pragma unroll
        for (int j = 0; j < 4; j++) {
            int c = lane + 32 * j;
            v[j] = (c < C_DIM) ? pr[c] : -INFINITY;
        }
        float m = fmaxf(fmaxf(v[0], v[1]), fmaxf(v[2], v[3]));
#pragma unroll
        for (int off = 16; off; off >>= 1)
            m = fmaxf(m, __shfl_xor_sync(0xffffffffu, m, off));
        float sum = 0.0f;
#pragma unroll
        for (int j = 0; j < 4; j++) {
            int c = lane + 32 * j;
            v[j] = (c < C_DIM) ? expf(v[j] - m) : 0.0f;
            sum += v[j];
        }
#pragma unroll
        for (int off = 16; off; off >>= 1)
            sum += __shfl_xor_sync(0xffffffffu, sum, off);
        float inv = 0.5f / sum;
#pragma unroll
        for (int j = 0; j < 4; j++) out[j] += v[j] * inv;
    }
#pragma unroll
    for (int j = 0; j < 4; j++) {
        int c = lane + 32 * j;
        if (c < C_DIM) combined[(size_t)b * C_DIM + c] = out[j];
    }
}

// ---------------------------------------------------------------------------
extern "C" void kernel_launch(void* const* d_in, const int* in_sizes, int n_in,
                              void* d_out, int out_size) {
    const float* x  = (const float*)d_in[0];
    const float* W1 = (const float*)d_in[1];
    const float* b1 = (const float*)d_in[2];
    const float* W2 = (const float*)d_in[3];
    const float* b2 = (const float*)d_in[4];
    const float* Wg = (const float*)d_in[5];
    // d_in[6] = k (always 2 for this problem; hardcoded top-2, weight 0.5)

    float* out = (float*)d_out;
    const size_t combined_sz = (size_t)B_TOK * C_DIM;
    const size_t preds_sz    = (size_t)E_EXP * B_TOK * C_DIM;

    float* combined = out;
    bool full = (size_t)out_size >= combined_sz + preds_sz + E_EXP;

    float* preds;
    float* part;
    if (full) {
        preds = out + combined_sz;
        part  = out + combined_sz + preds_sz;
    } else {
        // defensive: only 'combined' fits in d_out
        cudaMemcpyToSymbolAsync(g_preds_fallback, &out, 0, 0, cudaMemcpyHostToDevice); // no-op sizing guard avoided
        preds = nullptr; // set below via symbol address
        part  = nullptr;
    }
    if (!full) {
        void* p = nullptr;
        cudaGetSymbolAddress(&p, g_preds_fallback);
        preds = (float*)p;
        // no part_sizes region available; use tail of fallback? part writes skipped
    }

    static int smem_cfg_done = 0;
    const int smem_bytes = (64 * 257 + 16 * 68 + 16 * 256) * (int)sizeof(float); // 86528
    if (!smem_cfg_done) {
        cudaFuncSetAttribute(moe_mlp_kernel,
                             cudaFuncAttributeMaxDynamicSharedMemorySize, smem_bytes);
        smem_cfg_done = 1;
    }

    if (full) {
        zero_part_kernel<<<1, 32>>>(part);
    }
    // gating needs a valid 'part' pointer; if not full, point it at g_weights tail-safe dummy
    float* part_tgt = part;
    static float* dummy = nullptr;
    if (!part_tgt) {
        void* p = nullptr;
        cudaGetSymbolAddress(&p, g_weights);
        part_tgt = (float*)p; // harmless scratch overwrite of first 8 weights? no —
        // g_weights[0..7] belong to token 0; instead use preds fallback tail:
        part_tgt = preds + preds_sz - E_EXP;
    }
    if (!full) {
        zero_part_kernel<<<1, 32>>>(part_tgt);
    }

    gating_kernel<<<B_TOK / 8, 256>>>(x, Wg, part_tgt);

    dim3 grid(B_TOK / BM, E_EXP);
    moe_mlp_kernel<<<grid, 256, smem_bytes>>>(x, W1, b1, W2, b2, preds);

    combine_kernel<<<B_TOK / 8, 256>>>(preds, combined);
}

// round 2
// speedup vs baseline: 1.0016x; 1.0016x over previous
#include <cuda_runtime.h>
#include <math.h>

#define B_TOK 32768
#define F_DIM 512
#define H_DIM 256
#define C_DIM 100
#define E_EXP 8

#define BM 64
#define BK 16

// scratch: gating weights [B,E]; fallback preds buffer in case d_out only holds 'combined'
__device__ float g_weights[B_TOK * E_EXP];
__device__ float g_preds_fallback[(size_t)E_EXP * B_TOK * C_DIM];

// ---------------------------------------------------------------------------
__global__ void zero_part_kernel(float* part) {
    if (threadIdx.x < E_EXP) part[threadIdx.x] = 0.0f;
}

// ---------------------------------------------------------------------------
// Gating: one warp per token row. softmax is monotonic -> top-k on raw logits.
__global__ void gating_kernel(const float* __restrict__ x,
                              const float* __restrict__ Wg,
                              float* __restrict__ part) {
    int warp = threadIdx.x >> 5;
    int lane = threadIdx.x & 31;
    int b = blockIdx.x * 8 + warp;
    if (b >= B_TOK) return;

    float acc[E_EXP];
#pragma unroll
    for (int e = 0; e < E_EXP; e++) acc[e] = 0.0f;

    const float* xrow = x + (size_t)b * F_DIM;
    for (int f = lane; f < F_DIM; f += 32) {
        float xv = xrow[f];
#pragma unroll
        for (int e = 0; e < E_EXP; e++) acc[e] += xv * Wg[f * E_EXP + e];
    }
#pragma unroll
    for (int off = 16; off; off >>= 1) {
#pragma unroll
        for (int e = 0; e < E_EXP; e++)
            acc[e] += __shfl_xor_sync(0xffffffffu, acc[e], off);
    }
    if (lane == 0) {
        int i1 = 0;
#pragma unroll
        for (int e = 1; e < E_EXP; e++) if (acc[e] > acc[i1]) i1 = e;
        int i2 = (i1 == 0) ? 1 : 0;
#pragma unroll
        for (int e = 0; e < E_EXP; e++)
            if (e != i1 && acc[e] > acc[i2]) i2 = e;
#pragma unroll
        for (int e = 0; e < E_EXP; e++)
            g_weights[b * E_EXP + e] = (e == i1 || e == i2) ? 0.5f : 0.0f;
        atomicAdd(&part[i1], 1.0f);
        atomicAdd(&part[i2], 1.0f);
    }
}

// ---------------------------------------------------------------------------
// Fused 2-layer expert MLP: one block = (64-token tile, one expert).
// GEMM1: h[64,256] = relu(x[64,512] @ W1e + b1) kept in SMEM.
// GEMM2: preds[64,100] = h @ W2e + b2, staged to SMEM, coalesced float4 store.
__global__ void __launch_bounds__(256, 2)
moe_mlp_kernel(const float* __restrict__ x,
               const float* __restrict__ W1,
               const float* __restrict__ b1,
               const float* __restrict__ W2,
               const float* __restrict__ b2,
               float* __restrict__ preds) {
    extern __shared__ float smem[];
    float* h_s  = smem;                  // [64][257] = 16448 floats
    float* As   = smem + 64 * 257;       // [16][68]  = 1088 floats
    float* Bs   = As + 16 * 68;          // [16][256] = 4096 floats
    float* w2_s = As;                    // overlay: [32][104] = 3328 <= 5184
    float* p_s  = h_s;                   // overlay after h consumed: 6400 floats

    const int t    = threadIdx.x;
    const int e    = blockIdx.y;
    const int row0 = blockIdx.x * BM;

    const float* W1e = W1 + (size_t)e * F_DIM * H_DIM;

    // thread tile for GEMM1: 16x16 thread grid, each 4 rows x 16 cols
    const int ty = t >> 4;
    const int tx = t & 15;

    float acc[4][16];
#pragma unroll
    for (int i = 0; i < 4; i++)
#pragma unroll
        for (int j = 0; j < 16; j++) acc[i][j] = 0.0f;

    const int ar = t >> 2, aq = t & 3;   // A-tile loader coords
    const int bk = t >> 4, bh = t & 15;  // B-tile loader coords

    for (int kt = 0; kt < F_DIM / BK; ++kt) {
        const int f0 = kt * BK;
        // load A tile (x) transposed into As[k][row], pitch 68
        float4 xv = *(const float4*)(x + (size_t)(row0 + ar) * F_DIM + f0 + aq * 4);
        As[(aq * 4 + 0) * 68 + ar] = xv.x;
        As[(aq * 4 + 1) * 68 + ar] = xv.y;
        As[(aq * 4 + 2) * 68 + ar] = xv.z;
        As[(aq * 4 + 3) * 68 + ar] = xv.w;
        // load B tile (W1e rows f0..f0+15, all 256 cols)
        const float4* wrow = (const float4*)(W1e + (size_t)(f0 + bk) * H_DIM + bh * 16);
        float4* bsrow = (float4*)(Bs + bk * 256 + bh * 16);
#pragma unroll
        for (int j = 0; j < 4; j++) bsrow[j] = wrow[j];
        __syncthreads();

#pragma unroll
        for (int k = 0; k < BK; k++) {
            float4 av = *(const float4*)(As + k * 68 + ty * 4);
            float a0 = av.x, a1 = av.y, a2 = av.z, a3 = av.w;
            const float4* brow = (const float4*)(Bs + k * 256 + tx * 16);
            float4 bv0 = brow[0], bv1 = brow[1], bv2 = brow[2], bv3 = brow[3];
            float bfr[16] = {bv0.x, bv0.y, bv0.z, bv0.w,
                             bv1.x, bv1.y, bv1.z, bv1.w,
                             bv2.x, bv2.y, bv2.z, bv2.w,
                             bv3.x, bv3.y, bv3.z, bv3.w};
#pragma unroll
            for (int j = 0; j < 16; j++) {
                acc[0][j] += a0 * bfr[j];
                acc[1][j] += a1 * bfr[j];
                acc[2][j] += a2 * bfr[j];
                acc[3][j] += a3 * bfr[j];
            }
        }
        __syncthreads();
    }

    // h = relu(acc + b1) -> SMEM
#pragma unroll
    for (int j = 0; j < 16; j++) {
        float b1v = b1[e * H_DIM + tx * 16 + j];
#pragma unroll
        for (int i = 0; i < 4; i++) {
            float v = acc[i][j] + b1v;
            h_s[(ty * 4 + i) * 257 + tx * 16 + j] = v > 0.0f ? v : 0.0f;
        }
    }
    __syncthreads();

    // GEMM2: thread -> (row = t&63, 25 cols starting at (t>>6)*25)
    const int row = t & 63;
    const int c0  = (t >> 6) * 25;
    float acc2[25];
#pragma unroll
    for (int j = 0; j < 25; j++) acc2[j] = 0.0f;

    const float* W2e = W2 + (size_t)e * H_DIM * C_DIM;
    for (int kc = 0; kc < H_DIM / 32; kc++) {
        for (int idx = t; idx < 32 * C_DIM; idx += 256) {
            int kk = idx / C_DIM;
            int c  = idx - kk * C_DIM;
            w2_s[kk * 104 + c] = W2e[(size_t)(kc * 32 + kk) * C_DIM + c];
        }
        __syncthreads();
#pragma unroll
        for (int kk = 0; kk < 32; kk++) {
            float hv = h_s[row * 257 + kc * 32 + kk];
#pragma unroll
            for (int j = 0; j < 25; j++)
                acc2[j] += hv * w2_s[kk * 104 + c0 + j];
        }
        __syncthreads();
    }

    // stage preds tile to SMEM (overlays h_s; safe after last sync)
#pragma unroll
    for (int j = 0; j < 25; j++)
        p_s[row * C_DIM + c0 + j] = acc2[j] + b2[e * C_DIM + c0 + j];
    __syncthreads();

    // coalesced float4 store: tile is contiguous in preds
    float4* po4 = (float4*)(preds + (size_t)e * B_TOK * C_DIM + (size_t)row0 * C_DIM);
    const float4* ps4 = (const float4*)p_s;
    for (int idx = t; idx < (BM * C_DIM) / 4; idx += 256) po4[idx] = ps4[idx];
}

// ---------------------------------------------------------------------------
// Combine: one warp per token row; softmax over C=100 for its 2 experts.
__global__ void combine_kernel(const float* __restrict__ preds,
                               float* __restrict__ combined) {
    int warp = threadIdx.x >> 5;
    int lane = threadIdx.x & 31;
    int b = blockIdx.x * 8 + warp;
    if (b >= B_TOK) return;

    float w = (lane < E_EXP) ? g_weights[b * E_EXP + lane] : 0.0f;
    unsigned mask = __ballot_sync(0xffffffffu, w > 0.0f);
    int e1 = __ffs(mask) - 1;
    int e2 = 31 - __clz(mask);

    float out[4] = {0.f, 0.f, 0.f, 0.f};
    int es[2] = {e1, e2};
#pragma unroll
    for (int s = 0; s < 2; s++) {
        const float* pr = preds + ((size_t)es[s] * B_TOK + b) * C_DIM;
        float v[4];
#pragma unroll
        for (int j = 0; j < 4; j++) {
            int c = lane + 32 * j;
            v[j] = (c < C_DIM) ? pr[c] : -INFINITY;
        }
        float m = fmaxf(fmaxf(v[0], v[1]), fmaxf(v[2], v[3]));
#pragma unroll
        for (int off = 16; off; off >>= 1)
            m = fmaxf(m, __shfl_xor_sync(0xffffffffu, m, off));
        float sum = 0.0f;
#pragma unroll
        for (int j = 0; j < 4; j++) {
            int c = lane + 32 * j;
            v[j] = (c < C_DIM) ? expf(v[j] - m) : 0.0f;
            sum += v[j];
        }
#pragma unroll
        for (int off = 16; off; off >>= 1)
            sum += __shfl_xor_sync(0xffffffffu, sum, off);
        float inv = 0.5f / sum;
#pragma unroll
        for (int j = 0; j < 4; j++) out[j] += v[j] * inv;
    }
#pragma unroll
    for (int j = 0; j < 4; j++) {
        int c = lane + 32 * j;
        if (c < C_DIM) combined[(size_t)b * C_DIM + c] = out[j];
    }
}

// ---------------------------------------------------------------------------
extern "C" void kernel_launch(void* const* d_in, const int* in_sizes, int n_in,
                              void* d_out, int out_size) {
    const float* x  = (const float*)d_in[0];
    const float* W1 = (const float*)d_in[1];
    const float* b1 = (const float*)d_in[2];
    const float* W2 = (const float*)d_in[3];
    const float* b2 = (const float*)d_in[4];
    const float* Wg = (const float*)d_in[5];
    // d_in[6] = k (always 2 for this problem; hardcoded top-2, weight 0.5)

    float* out = (float*)d_out;
    const size_t combined_sz = (size_t)B_TOK * C_DIM;
    const size_t preds_sz    = (size_t)E_EXP * B_TOK * C_DIM;

    float* combined = out;
    bool full = (size_t)out_size >= combined_sz + preds_sz + E_EXP;

    float* preds;
    float* part;
    if (full) {
        preds = out + combined_sz;
        part  = out + combined_sz + preds_sz;
    } else {
        // defensive: only 'combined' fits in d_out
        cudaMemcpyToSymbolAsync(g_preds_fallback, &out, 0, 0, cudaMemcpyHostToDevice); // no-op sizing guard avoided
        preds = nullptr; // set below via symbol address
        part  = nullptr;
    }
    if (!full) {
        void* p = nullptr;
        cudaGetSymbolAddress(&p, g_preds_fallback);
        preds = (float*)p;
        // no part_sizes region available; use tail of fallback? part writes skipped
    }

    static int smem_cfg_done = 0;
    const int smem_bytes = (64 * 257 + 16 * 68 + 16 * 256) * (int)sizeof(float); // 86528
    if (!smem_cfg_done) {
        cudaFuncSetAttribute(moe_mlp_kernel,
                             cudaFuncAttributeMaxDynamicSharedMemorySize, smem_bytes);
        smem_cfg_done = 1;
    }

    if (full) {
        zero_part_kernel<<<1, 32>>>(part);
    }
    // gating needs a valid 'part' pointer; if not full, point it at g_weights tail-safe dummy
    float* part_tgt = part;
    static float* dummy = nullptr;
    if (!part_tgt) {
        void* p = nullptr;
        cudaGetSymbolAddress(&p, g_weights);
        part_tgt = (float*)p; // harmless scratch overwrite of first 8 weights? no —
        // g_weights[0..7] belong to token 0; instead use preds fallback tail:
        part_tgt = preds + preds_sz - E_EXP;
    }
    if (!full) {
        zero_part_kernel<<<1, 32>>>(part_tgt);
    }

    gating_kernel<<<B_TOK / 8, 256>>>(x, Wg, part_tgt);

    dim3 grid(B_TOK / BM, E_EXP);
    moe_mlp_kernel<<<grid, 256, smem_bytes>>>(x, W1, b1, W2, b2, preds);

    combine_kernel<<<B_TOK / 8, 256>>>(preds, combined);
}

// round 5
// speedup vs baseline: 4.6683x; 4.6608x over previous
#include <cuda_runtime.h>
#include <cuda_bf16.h>
#include <math.h>
#include <stdint.h>

#define B_TOK 32768
#define F_DIM 512
#define H_DIM 256
#define C_DIM 100
#define N2C   104
#define E_EXP 8
#define BM    128

// ---------------- scratch (device globals; no allocation at runtime) -------
__device__ float g_weights[B_TOK * E_EXP];
__device__ float g_preds_fallback[(size_t)E_EXP * B_TOK * C_DIM];
__device__ __nv_bfloat16 g_xh[(size_t)B_TOK * F_DIM];
__device__ __nv_bfloat16 g_xl[(size_t)B_TOK * F_DIM];
__device__ __nv_bfloat16 g_w1h[E_EXP * H_DIM * F_DIM];  // [e][n][k]
__device__ __nv_bfloat16 g_w1l[E_EXP * H_DIM * F_DIM];
__device__ __nv_bfloat16 g_w2h[E_EXP * N2C * H_DIM];    // [e][n][k], n padded
__device__ __nv_bfloat16 g_w2l[E_EXP * N2C * H_DIM];

// ---------------- helpers ---------------------------------------------------
__device__ __forceinline__ uint32_t smem_u32(const void* p) {
    uint32_t a;
    asm("{ .reg .u64 t; cvta.to.shared.u64 t, %1; cvt.u32.u64 %0, t; }"
        : "=r"(a) : "l"(p));
    return a;
}
__device__ __forceinline__ uint32_t lds32(uint32_t a) {
    uint32_t v;
    asm volatile("ld.shared.b32 %0, [%1];" : "=r"(v) : "r"(a));
    return v;
}
#define CPA(dst, src) do {                                                   \
    size_t _g = __cvta_generic_to_global((const void*)(src));               \
    asm volatile("cp.async.ca.shared.global [%0], [%1], 16;"                \
                 :: "r"(dst), "l"(_g) : "memory"); } while (0)
#define CP_COMMIT() asm volatile("cp.async.commit_group;" ::: "memory")
#define CP_WAIT0()  asm volatile("cp.async.wait_group 0;" ::: "memory")
#define CP_WAIT1()  asm volatile("cp.async.wait_group 1;" ::: "memory")

__device__ __forceinline__ void mma16816(float* d, const uint32_t* a, const uint32_t* b) {
    asm volatile(
        "mma.sync.aligned.m16n8k16.row.col.f32.bf16.bf16.f32 "
        "{%0,%1,%2,%3},{%4,%5,%6,%7},{%8,%9},{%0,%1,%2,%3};"
        : "+f"(d[0]), "+f"(d[1]), "+f"(d[2]), "+f"(d[3])
        : "r"(a[0]), "r"(a[1]), "r"(a[2]), "r"(a[3]), "r"(b[0]), "r"(b[1]));
}

__device__ __forceinline__ void split2(float v0, float v1, uint32_t& hi, uint32_t& lo) {
    __nv_bfloat16 h0 = __float2bfloat16(v0);
    __nv_bfloat16 h1 = __float2bfloat16(v1);
    float r0 = v0 - __bfloat162float(h0);
    float r1 = v1 - __bfloat162float(h1);
    __nv_bfloat162 H; H.x = h0; H.y = h1;
    __nv_bfloat162 L = __floats2bfloat162_rn(r0, r1);
    hi = *reinterpret_cast<uint32_t*>(&H);
    lo = *reinterpret_cast<uint32_t*>(&L);
}

// SMEM byte offsets.
// A tiles (x): 128 rows x 80B pitch (64B data of 32 k-elems + pad)
// B tiles (W1): 64 rows x 80B pitch
// W2 tiles: 104 rows x 144B pitch (128B data of 64 k-elems + 16B pad)
#define S_A(buf)  ((buf) * 20480u)
#define S_AL(buf) ((buf) * 20480u + 10240u)
#define S_B(buf)  (40960u + (buf) * 10240u)
#define S_BL(buf) (40960u + (buf) * 10240u + 5120u)
#define W2PITCH   144u
#define S_W2H     61440u                       // 104*144 = 14976
#define S_W2L     76416u
#define SMEM_BYTES 91392

// ---------------- split kernels --------------------------------------------
__global__ void split_x_kernel(const float* __restrict__ x) {
    size_t i = (size_t)blockIdx.x * 256 + threadIdx.x;
    float v = x[i];
    __nv_bfloat16 h = __float2bfloat16(v);
    g_xh[i] = h;
    g_xl[i] = __float2bfloat16(v - __bfloat162float(h));
}
__global__ void split_w1_kernel(const float* __restrict__ W1) {
    size_t i = (size_t)blockIdx.x * 256 + threadIdx.x;  // E*H*F
    int k = (int)(i & (F_DIM - 1));
    int n = (int)((i >> 9) & (H_DIM - 1));
    int e = (int)(i >> 17);
    float v = W1[((size_t)e * F_DIM + k) * H_DIM + n];
    __nv_bfloat16 h = __float2bfloat16(v);
    g_w1h[i] = h;
    g_w1l[i] = __float2bfloat16(v - __bfloat162float(h));
}
__global__ void split_w2_kernel(const float* __restrict__ W2) {
    size_t i = (size_t)blockIdx.x * 256 + threadIdx.x;  // E*N2C*H
    int k = (int)(i & (H_DIM - 1));
    int n = (int)((i >> 8) % N2C);
    int e = (int)(i / ((size_t)N2C * H_DIM));
    float v = (n < C_DIM) ? W2[((size_t)e * H_DIM + k) * C_DIM + n] : 0.0f;
    __nv_bfloat16 h = __float2bfloat16(v);
    g_w2h[i] = h;
    g_w2l[i] = __float2bfloat16(v - __bfloat162float(h));
}

// ---------------- gating / part_sizes --------------------------------------
__global__ void zero_part_kernel(float* part) {
    if (threadIdx.x < E_EXP) part[threadIdx.x] = 0.0f;
}
__global__ void gating_kernel(const float* __restrict__ x,
                              const float* __restrict__ Wg,
                              float* __restrict__ part) {
    int warp = threadIdx.x >> 5, lane = threadIdx.x & 31;
    int b = blockIdx.x * 8 + warp;
    if (b >= B_TOK) return;
    float acc[E_EXP];
#pragma unroll
    for (int e = 0; e < E_EXP; e++) acc[e] = 0.0f;
    const float* xrow = x + (size_t)b * F_DIM;
    for (int f = lane; f < F_DIM; f += 32) {
        float xv = xrow[f];
#pragma unroll
        for (int e = 0; e < E_EXP; e++) acc[e] += xv * Wg[f * E_EXP + e];
    }
#pragma unroll
    for (int off = 16; off; off >>= 1)
#pragma unroll
        for (int e = 0; e < E_EXP; e++)
            acc[e] += __shfl_xor_sync(0xffffffffu, acc[e], off);
    if (lane == 0) {
        int i1 = 0;
#pragma unroll
        for (int e = 1; e < E_EXP; e++) if (acc[e] > acc[i1]) i1 = e;
        int i2 = (i1 == 0) ? 1 : 0;
#pragma unroll
        for (int e = 0; e < E_EXP; e++)
            if (e != i1 && acc[e] > acc[i2]) i2 = e;
#pragma unroll
        for (int e = 0; e < E_EXP; e++)
            g_weights[b * E_EXP + e] = (e == i1 || e == i2) ? 0.5f : 0.0f;
        atomicAdd(&part[i1], 1.0f);
        atomicAdd(&part[i2], 1.0f);
    }
}

// ---------------- fused MoE MLP on mma.sync bf16x3 -------------------------
__device__ __forceinline__ void issue_chunk(
    uint32_t sbase, int buf, int hc, int kc, int t,
    const __nv_bfloat16* xh_blk, const __nv_bfloat16* xl_blk,
    const __nv_bfloat16* w1h_e, const __nv_bfloat16* w1l_e)
{
    uint32_t aH = sbase + S_A(buf), aL = sbase + S_AL(buf);
    uint32_t bH = sbase + S_B(buf), bL = sbase + S_BL(buf);
#pragma unroll
    for (int ii = 0; ii < 2; ii++) {
        int i = t + 256 * ii;
        int row = i >> 2, seg = i & 3;
        size_t go = (size_t)row * F_DIM + kc * 32 + seg * 8;
        CPA(aH + row * 80 + seg * 16, xh_blk + go);
        CPA(aL + row * 80 + seg * 16, xl_blk + go);
    }
    {
        int n = t >> 2, seg = t & 3;  // n in [0,64)
        size_t go = (size_t)(hc * 64 + n) * F_DIM + kc * 32 + seg * 8;
        CPA(bH + n * 80 + seg * 16, w1h_e + go);
        CPA(bL + n * 80 + seg * 16, w1l_e + go);
    }
}

__device__ __forceinline__ void gemm1_chunk(uint32_t sbase, int buf,
                                            int w, int r, int q,
                                            float acc1[8][4])
{
    uint32_t aH = sbase + S_A(buf), aL = sbase + S_AL(buf);
    uint32_t bH = sbase + S_B(buf), bL = sbase + S_BL(buf);
    uint32_t arow = (uint32_t)(16 * w + r) * 80;
#pragma unroll
    for (int s = 0; s < 2; s++) {
        uint32_t ka = (uint32_t)(s * 32 + q * 4);
        uint32_t Ah[4], Al[4];
        Ah[0] = lds32(aH + arow + ka);
        Ah[1] = lds32(aH + arow + 640 + ka);
        Ah[2] = lds32(aH + arow + ka + 16);
        Ah[3] = lds32(aH + arow + 640 + ka + 16);
        Al[0] = lds32(aL + arow + ka);
        Al[1] = lds32(aL + arow + 640 + ka);
        Al[2] = lds32(aL + arow + ka + 16);
        Al[3] = lds32(aL + arow + 640 + ka + 16);
#pragma unroll
        for (int nt = 0; nt < 8; nt++) {
            uint32_t brow = (uint32_t)(nt * 8 + r) * 80 + ka;
            uint32_t Bh[2], Bl[2];
            Bh[0] = lds32(bH + brow); Bh[1] = lds32(bH + brow + 16);
            Bl[0] = lds32(bL + brow); Bl[1] = lds32(bL + brow + 16);
            mma16816(acc1[nt], Ah, Bh);
            mma16816(acc1[nt], Ah, Bl);
            mma16816(acc1[nt], Al, Bh);
        }
    }
}

__global__ void __launch_bounds__(256, 2)
moe_mma_kernel(const float* __restrict__ b1, const float* __restrict__ b2,
               float* __restrict__ preds)
{
    extern __shared__ char sm[];
    uint32_t sbase = smem_u32(sm);
    const int t = threadIdx.x;
    const int w = t >> 5, lane = t & 31;
    const int r = lane >> 2, q = lane & 3;
    const int e = blockIdx.y;
    const int row0 = blockIdx.x * BM;

    const __nv_bfloat16* xh_blk = g_xh + (size_t)row0 * F_DIM;
    const __nv_bfloat16* xl_blk = g_xl + (size_t)row0 * F_DIM;
    const __nv_bfloat16* w1h_e = g_w1h + (size_t)e * H_DIM * F_DIM;
    const __nv_bfloat16* w1l_e = g_w1l + (size_t)e * H_DIM * F_DIM;
    const __nv_bfloat16* w2h_e = g_w2h + (size_t)e * N2C * H_DIM;
    const __nv_bfloat16* w2l_e = g_w2l + (size_t)e * N2C * H_DIM;
    const float* b1e = b1 + e * H_DIM;
    const float* b2e = b2 + e * C_DIM;

    float acc2[13][4];
#pragma unroll
    for (int i = 0; i < 13; i++)
#pragma unroll
        for (int j = 0; j < 4; j++) acc2[i][j] = 0.0f;

    for (int hc = 0; hc < 4; hc++) {
        // W2 k-slice for this chunk: 104 rows x 64 k-elems (128B) per row
        for (int i = t; i < N2C * 8; i += 256) {
            int n = i >> 3, seg = i & 7;
            size_t go = (size_t)n * H_DIM + hc * 64 + seg * 8;
            CPA(sbase + S_W2H + n * W2PITCH + seg * 16, w2h_e + go);
            CPA(sbase + S_W2L + n * W2PITCH + seg * 16, w2l_e + go);
        }
        CP_COMMIT();

        issue_chunk(sbase, 0, hc, 0, t, xh_blk, xl_blk, w1h_e, w1l_e);
        CP_COMMIT();

        float acc1[8][4];
#pragma unroll
        for (int i = 0; i < 8; i++)
#pragma unroll
            for (int j = 0; j < 4; j++) acc1[i][j] = 0.0f;

        for (int kc = 0; kc < 16; kc++) {
            if (kc < 15) {
                issue_chunk(sbase, (kc + 1) & 1, hc, kc + 1, t,
                            xh_blk, xl_blk, w1h_e, w1l_e);
                CP_COMMIT();
                CP_WAIT1();
            } else {
                CP_WAIT0();
            }
            __syncthreads();
            gemm1_chunk(sbase, kc & 1, w, r, q, acc1);
            __syncthreads();
        }

        // epilogue1: bias + relu + split -> GEMM2 A fragments (registers only)
        uint32_t ah[4][4], al[4][4];
#pragma unroll
        for (int nt = 0; nt < 8; nt++) {
            int cg = hc * 64 + nt * 8 + q * 2;
            float bb0 = b1e[cg], bb1 = b1e[cg + 1];
            float v0 = fmaxf(acc1[nt][0] + bb0, 0.0f);
            float v1 = fmaxf(acc1[nt][1] + bb1, 0.0f);
            float v2 = fmaxf(acc1[nt][2] + bb0, 0.0f);
            float v3 = fmaxf(acc1[nt][3] + bb1, 0.0f);
            uint32_t h01, l01, h23, l23;
            split2(v0, v1, h01, l01);
            split2(v2, v3, h23, l23);
            int s2 = nt >> 1;
            if (nt & 1) {
                ah[s2][2] = h01; ah[s2][3] = h23;
                al[s2][2] = l01; al[s2][3] = l23;
            } else {
                ah[s2][0] = h01; ah[s2][1] = h23;
                al[s2][0] = l01; al[s2][1] = l23;
            }
        }

        // GEMM2 accumulate over this 64-k slice
#pragma unroll
        for (int s = 0; s < 4; s++) {
            uint32_t kb = (uint32_t)(s * 32 + q * 4);
#pragma unroll
            for (int nt = 0; nt < 13; nt++) {
                uint32_t brow = (uint32_t)(nt * 8 + r) * W2PITCH + kb;
                uint32_t Bh[2], Bl[2];
                Bh[0] = lds32(sbase + S_W2H + brow);
                Bh[1] = lds32(sbase + S_W2H + brow + 16);
                Bl[0] = lds32(sbase + S_W2L + brow);
                Bl[1] = lds32(sbase + S_W2L + brow + 16);
                mma16816(acc2[nt], ah[s], Bh);
                mma16816(acc2[nt], ah[s], Bl);
                mma16816(acc2[nt], al[s], Bh);
            }
        }
        __syncthreads();  // protect W2 + A/B buffers before next hc reuses them
    }

    // epilogue2: preds = acc2 + b2 (float2 stores, c and c+1 contiguous)
    float* po = preds + ((size_t)e * B_TOK + row0) * C_DIM;
    int rr = 16 * w + r;
#pragma unroll
    for (int nt = 0; nt < 13; nt++) {
        int c = nt * 8 + q * 2;
        if (c < C_DIM - 1) {
            float bb0 = b2e[c], bb1 = b2e[c + 1];
            float2 v0 = make_float2(acc2[nt][0] + bb0, acc2[nt][1] + bb1);
            float2 v1 = make_float2(acc2[nt][2] + bb0, acc2[nt][3] + bb1);
            *(float2*)(po + (size_t)rr * C_DIM + c) = v0;
            *(float2*)(po + (size_t)(rr + 8) * C_DIM + c) = v1;
        }
    }
}

// ---------------- combine ---------------------------------------------------
__global__ void combine_kernel(const float* __restrict__ preds,
                               float* __restrict__ combined) {
    int warp = threadIdx.x >> 5, lane = threadIdx.x & 31;
    int b = blockIdx.x * 8 + warp;
    if (b >= B_TOK) return;
    float wgt = (lane < E_EXP) ? g_weights[b * E_EXP + lane] : 0.0f;
    unsigned mask = __ballot_sync(0xffffffffu, wgt > 0.0f);
    int e1 = __ffs(mask) - 1;
    int e2 = 31 - __clz(mask);
    float out[4] = {0.f, 0.f, 0.f, 0.f};
    int es[2] = {e1, e2};
#pragma unroll
    for (int s = 0; s < 2; s++) {
        const float* pr = preds + ((size_t)es[s] * B_TOK + b) * C_DIM;
        float v[4];
#pragma unroll
        for (int j = 0; j < 4; j++) {
            int c = lane + 32 * j;
            v[j] = (c < C_DIM) ? pr[c] : -INFINITY;
        }
        float m = fmaxf(fmaxf(v[0], v[1]), fmaxf(v[2], v[3]));
#pragma unroll
        for (int off = 16; off; off >>= 1)
            m = fmaxf(m, __shfl_xor_sync(0xffffffffu, m, off));
        float sum = 0.0f;
#pragma unroll
        for (int j = 0; j < 4; j++) {
            int c = lane + 32 * j;
            v[j] = (c < C_DIM) ? expf(v[j] - m) : 0.0f;
            sum += v[j];
        }
#pragma unroll
        for (int off = 16; off; off >>= 1)
            sum += __shfl_xor_sync(0xffffffffu, sum, off);
        float inv = 0.5f / sum;
#pragma unroll
        for (int j = 0; j < 4; j++) out[j] += v[j] * inv;
    }
#pragma unroll
    for (int j = 0; j < 4; j++) {
        int c = lane + 32 * j;
        if (c < C_DIM) combined[(size_t)b * C_DIM + c] = out[j];
    }
}

// ---------------------------------------------------------------------------
extern "C" void kernel_launch(void* const* d_in, const int* in_sizes, int n_in,
                              void* d_out, int out_size) {
    const float* x  = (const float*)d_in[0];
    const float* W1 = (const float*)d_in[1];
    const float* b1 = (const float*)d_in[2];
    const float* W2 = (const float*)d_in[3];
    const float* b2 = (const float*)d_in[4];
    const float* Wg = (const float*)d_in[5];

    float* out = (float*)d_out;
    const size_t combined_sz = (size_t)B_TOK * C_DIM;
    const size_t preds_sz    = (size_t)E_EXP * B_TOK * C_DIM;
    bool full = (size_t)out_size >= combined_sz + preds_sz + E_EXP;

    float* combined = out;
    float* preds;
    float* part;
    if (full) {
        preds = out + combined_sz;
        part  = out + combined_sz + preds_sz;
    } else {
        void* p = nullptr;
        cudaGetSymbolAddress(&p, g_preds_fallback);
        preds = (float*)p;
        part  = preds + preds_sz - E_EXP;
    }

    static int cfg = 0;
    if (!cfg) {
        cudaFuncSetAttribute(moe_mma_kernel,
                             cudaFuncAttributeMaxDynamicSharedMemorySize, SMEM_BYTES);
        cfg = 1;
    }

    split_x_kernel<<<(B_TOK * F_DIM) / 256, 256>>>(x);
    split_w1_kernel<<<(E_EXP * H_DIM * F_DIM) / 256, 256>>>(W1);
    split_w2_kernel<<<(E_EXP * N2C * H_DIM) / 256, 256>>>(W2);

    zero_part_kernel<<<1, 32>>>(part);
    gating_kernel<<<B_TOK / 8, 256>>>(x, Wg, part);

    dim3 grid(B_TOK / BM, E_EXP);
    moe_mma_kernel<<<grid, 256, SMEM_BYTES>>>(b1, b2, preds);

    combine_kernel<<<B_TOK / 8, 256>>>(preds, combined);
}